// round 1
// baseline (speedup 1.0000x reference)
#include <cuda_runtime.h>
#include <cuda_bf16.h>
#include <math.h>

// Problem constants
#define Bn 32
#define CIN 96
#define Tt 288
#define Vv 25
#define Ss 3
#define Cc 96
#define Oo 288            // S*Cout
#define VP 28             // V padded to 28 (14 f32x2 pairs)
#define TT 32             // t's per CTA in pass 1
#define NTILES 9          // 288 / 32
#define WROW 290          // padded row length for sWt / sYt

typedef unsigned long long ull;

// z scratch, padded layout [b][c][t][28]
__device__ float g_z[(size_t)Bn * Cc * Tt * VP];
__device__ float g_mean[Cc];
__device__ float g_rstd[Cc];

__device__ __forceinline__ void fma2(ull &d, ull a, ull b) {
    asm("fma.rn.f32x2 %0, %1, %2, %0;" : "+l"(d) : "l"(a), "l"(b));
}
__device__ __forceinline__ ull dup2(float x) {
    ull r;
    asm("mov.b64 %0, {%1, %1};" : "=l"(r) : "f"(x));
    return r;
}
__device__ __forceinline__ float lo2(ull v) { return __uint_as_float((unsigned)(v & 0xffffffffull)); }
__device__ __forceinline__ float hi2(ull v) { return __uint_as_float((unsigned)(v >> 32)); }

// ---------------------------------------------------------------------------
// Pass 1: per (b, t-tile): y = W @ x[b,:,t,:] + bias ; z = sum_s y_s @ A_s
// written to g_z (padded).
// Shared layout (floats):
//   sWt [96][290]   : sWt[i][o] = W[o][i]                       27840
//   sYt [28][290]   : sYt[m][o] = y[o][m]                        8120
//   sX  [2][96][28] : double-buffered x slice                    5376
//   sA  [3][25][28] : A padded (cols 25..27 = 0)                 2100
//   sB  [288]       : bias                                        288
// total 43724 floats = 174896 bytes
// ---------------------------------------------------------------------------
__global__ void __launch_bounds__(256, 1)
pass1_kernel(const float* __restrict__ x, const float* __restrict__ A,
             const float* __restrict__ W, const float* __restrict__ bias) {
    extern __shared__ float smem[];
    float* sWt = smem;                  // 27840
    float* sYt = smem + 27840;          //  8120
    float* sX  = smem + 35960;          //  5376
    float* sA  = smem + 41336;          //  2100
    float* sB  = smem + 43436;          //   288

    const int tid = threadIdx.x;
    const int b   = blockIdx.y;
    const int t0  = blockIdx.x * TT;

    // ---- load weights (transposed), A (padded), bias ----
    for (int idx = tid; idx < Oo * CIN; idx += 256) {
        int o = idx / CIN, i = idx % CIN;
        sWt[i * WROW + o] = W[idx];
    }
    for (int idx = tid; idx < Ss * Vv * VP; idx += 256) {
        int s = idx / (Vv * VP);
        int r = idx % (Vv * VP);
        int n = r / VP, m = r % VP;
        sA[idx] = (m < Vv) ? A[(s * Vv + n) * Vv + m] : 0.0f;
    }
    for (int idx = tid; idx < Oo; idx += 256) sB[idx] = bias[idx];
    // zero pad columns of both x buffers
    for (int idx = tid; idx < 2 * CIN * (VP - Vv); idx += 256) {
        int buf = idx / (CIN * (VP - Vv));
        int r = idx % (CIN * (VP - Vv));
        int i = r / (VP - Vv), p = r % (VP - Vv);
        sX[buf * (CIN * VP) + i * VP + Vv + p] = 0.0f;
    }
    // initial x slice (t0) into buffer 0
    for (int idx = tid; idx < CIN * Vv; idx += 256) {
        int i = idx / Vv, n = idx % Vv;
        sX[i * VP + n] = x[((b * CIN + i) * Tt + t0) * Vv + n];
    }
    __syncthreads();

    // thread work mapping:
    // phase BIG (y = Wt^T x): 252 units = 36 o-blocks (8 o's) x 7 m-tiles (4 m's)
    const int mtB = tid % 7;
    const int obB = tid / 7;
    // phase SMALL (z = y A): 168 units = 24 c-blocks (4 c's) x 7 m-tiles (4 m's)
    const int mtS = tid % 7;
    const int cbS = tid / 7;

    for (int tt = 0; tt < TT; tt++) {
        const int t   = t0 + tt;
        const int buf = tt & 1;
        const int xoff = buf * (CIN * VP);

        // prefetch x slice for t+1 into registers
        float pf[10];
        const bool haveNext = (tt + 1 < TT);
        if (haveNext) {
            const int tn = t + 1;
#pragma unroll
            for (int r = 0; r < 10; r++) {
                int idx = tid + r * 256;
                if (idx < CIN * Vv) {
                    int i = idx / Vv, n = idx % Vv;
                    pf[r] = x[((b * CIN + i) * Tt + tn) * Vv + n];
                }
            }
        }

        // ---- phase BIG: y[o][m] = sum_k W[o][k] * x[k][m], f32x2 over o-pairs ----
        if (tid < 252) {
            const int o0 = obB * 8;
            const int m0 = mtB * 4;
            ull acc[4][4];
#pragma unroll
            for (int p = 0; p < 4; p++)
#pragma unroll
                for (int j = 0; j < 4; j++) acc[p][j] = 0ull;

            const float* wp = sWt + o0;
            const float* xp = sX + xoff + m0;
#pragma unroll 4
            for (int k = 0; k < CIN; k++) {
                ull w0 = *(const ull*)(wp + 0);
                ull w1 = *(const ull*)(wp + 2);
                ull w2 = *(const ull*)(wp + 4);
                ull w3 = *(const ull*)(wp + 6);
                ull xd0 = dup2(xp[0]);
                ull xd1 = dup2(xp[1]);
                ull xd2 = dup2(xp[2]);
                ull xd3 = dup2(xp[3]);
                fma2(acc[0][0], w0, xd0); fma2(acc[0][1], w0, xd1);
                fma2(acc[0][2], w0, xd2); fma2(acc[0][3], w0, xd3);
                fma2(acc[1][0], w1, xd0); fma2(acc[1][1], w1, xd1);
                fma2(acc[1][2], w1, xd2); fma2(acc[1][3], w1, xd3);
                fma2(acc[2][0], w2, xd0); fma2(acc[2][1], w2, xd1);
                fma2(acc[2][2], w2, xd2); fma2(acc[2][3], w2, xd3);
                fma2(acc[3][0], w3, xd0); fma2(acc[3][1], w3, xd1);
                fma2(acc[3][2], w3, xd2); fma2(acc[3][3], w3, xd3);
                wp += WROW;
                xp += VP;
            }
            // epilogue: add bias, store y transposed: sYt[m][o]
#pragma unroll
            for (int p = 0; p < 4; p++) {
                const int oo = o0 + 2 * p;
                const float blo = sB[oo], bhi = sB[oo + 1];
#pragma unroll
                for (int j = 0; j < 4; j++) {
                    const int m = m0 + j;
                    float2 v;
                    v.x = lo2(acc[p][j]) + blo;
                    v.y = hi2(acc[p][j]) + bhi;
                    *(float2*)(sYt + m * WROW + oo) = v;
                }
            }
        }
        __syncthreads();   // sYt ready; sX[buf^1] free

        // store prefetched x into the other buffer
        if (haveNext) {
#pragma unroll
            for (int r = 0; r < 10; r++) {
                int idx = tid + r * 256;
                if (idx < CIN * Vv) {
                    int i = idx / Vv, n = idx % Vv;
                    sX[(buf ^ 1) * (CIN * VP) + i * VP + n] = pf[r];
                }
            }
        }

        // ---- phase SMALL: z[c][m] = sum_{s,n} y[s*96+c][n] * A[s][n][m] ----
        if (tid < 168) {
            const int m0 = mtS * 4;
            const int c0 = cbS * 4;
            ull z0[4] = {0ull, 0ull, 0ull, 0ull};
            ull z1[4] = {0ull, 0ull, 0ull, 0ull};
#pragma unroll
            for (int s = 0; s < Ss; s++) {
                const float* yrow = sYt + (s * Cc + c0);
                const float* arow = sA + s * (Vv * VP) + m0;
#pragma unroll 5
                for (int n = 0; n < Vv; n++) {
                    ull ya = *(const ull*)(yrow);
                    ull yb = *(const ull*)(yrow + 2);
#pragma unroll
                    for (int j = 0; j < 4; j++) {
                        ull ad = dup2(arow[j]);
                        fma2(z0[j], ya, ad);
                        fma2(z1[j], yb, ad);
                    }
                    yrow += WROW;
                    arow += VP;
                }
            }
            // write z (padded layout)
            const int cstride = Tt * VP;
            int zbase = ((b * Cc + c0) * Tt + t) * VP + m0;
#pragma unroll
            for (int j = 0; j < 4; j++) {
                g_z[zbase + j]               = lo2(z0[j]);
                g_z[zbase + cstride + j]     = hi2(z0[j]);
                g_z[zbase + 2 * cstride + j] = lo2(z1[j]);
                g_z[zbase + 3 * cstride + j] = hi2(z1[j]);
            }
        }
        __syncthreads();   // sYt consumed; sX[buf^1] written
    }
}

// ---------------------------------------------------------------------------
// Pass 2: per-channel BN statistics over windowed z (out = window-avg of z).
// One CTA per channel; exact double-precision reduction, no atomics.
// ---------------------------------------------------------------------------
__global__ void __launch_bounds__(256)
pass2_kernel() {
    const int c = blockIdx.x;
    const int tid = threadIdx.x;
    __shared__ float sP[Tt * VP];
    __shared__ double red[512];

    double sum = 0.0, ss = 0.0;
    for (int b = 0; b < Bn; b++) {
        __syncthreads();
        const float* src = g_z + (size_t)(b * Cc + c) * Tt * VP;
        for (int i = tid; i < Tt * VP; i += 256) sP[i] = src[i];
        __syncthreads();
        for (int i = tid; i < Tt * Vv; i += 256) {
            int t = i / Vv, m = i % Vv;
            float v = 0.0f;
#pragma unroll
            for (int k = -2; k <= 2; k++) {
                int tk = t + k;
                if (tk >= 0 && tk < Tt) v += sP[tk * VP + m];
            }
            v *= 0.2f;
            sum += (double)v;
            ss  += (double)v * (double)v;
        }
    }
    red[tid] = sum;
    red[256 + tid] = ss;
    __syncthreads();
    for (int s2 = 128; s2 > 0; s2 >>= 1) {
        if (tid < s2) {
            red[tid] += red[tid + s2];
            red[256 + tid] += red[256 + tid + s2];
        }
        __syncthreads();
    }
    if (tid == 0) {
        const double N = (double)Bn * Tt * Vv;   // 230400
        double mean = red[0] / N;
        double var  = red[256] / N - mean * mean;
        g_mean[c] = (float)mean;
        g_rstd[c] = (float)(1.0 / sqrt(var + 1e-5));
    }
}

// ---------------------------------------------------------------------------
// Pass 3: window-avg + normalize + affine + relu, write final output.
// One CTA per (b, c) plane; fully coalesced output.
// ---------------------------------------------------------------------------
__global__ void __launch_bounds__(256)
pass3_kernel(const float* __restrict__ gamma, const float* __restrict__ beta,
             float* __restrict__ out) {
    const int c = blockIdx.x;
    const int b = blockIdx.y;
    const int tid = threadIdx.x;
    __shared__ float sP[Tt * VP];

    const float* src = g_z + (size_t)(b * Cc + c) * Tt * VP;
    for (int i = tid; i < Tt * VP; i += 256) sP[i] = src[i];
    __syncthreads();

    const float mean = g_mean[c];
    const float rstd = g_rstd[c];
    const float sc = rstd * gamma[c];
    const float sh = beta[c] - mean * sc;

    float* dst = out + (size_t)(b * Cc + c) * Tt * Vv;
    for (int i = tid; i < Tt * Vv; i += 256) {
        int t = i / Vv, m = i % Vv;
        float v = 0.0f;
#pragma unroll
        for (int k = -2; k <= 2; k++) {
            int tk = t + k;
            if (tk >= 0 && tk < Tt) v += sP[tk * VP + m];
        }
        v *= 0.2f;
        float o = fmaf(v, sc, sh);
        dst[i] = fmaxf(o, 0.0f);
    }
}

// ---------------------------------------------------------------------------
extern "C" void kernel_launch(void* const* d_in, const int* in_sizes, int n_in,
                              void* d_out, int out_size) {
    const float* x     = (const float*)d_in[0];
    const float* A     = (const float*)d_in[1];
    const float* W     = (const float*)d_in[2];
    const float* bias  = (const float*)d_in[3];
    const float* gamma = (const float*)d_in[4];
    const float* beta  = (const float*)d_in[5];
    float* out = (float*)d_out;

    const int smem1 = 43724 * 4;   // 174896 bytes
    cudaFuncSetAttribute(pass1_kernel, cudaFuncAttributeMaxDynamicSharedMemorySize, smem1);

    pass1_kernel<<<dim3(NTILES, Bn), 256, smem1>>>(x, A, W, bias);
    pass2_kernel<<<Cc, 256>>>();
    pass3_kernel<<<dim3(Cc, Bn), 256>>>(gamma, beta, out);
}